// round 10
// baseline (speedup 1.0000x reference)
#include <cuda_runtime.h>

#define NEMB        512
#define SORT_BLOCKS 16
#define QBLOCKS     512          // 1 element per thread: 512*512 = 262144
#define QTHREADS    512
#define LUT_SIZE    8192
#define LUT_CHUNK   (LUT_SIZE / QTHREADS)   // 16 buckets per thread

__device__ float        g_sorted_val[NEMB];
__device__ int          g_sorted_idx[NEMB];
__device__ float        g_loss_accum = 0.0f;
__device__ unsigned int g_ready = 0;
__device__ unsigned int g_done  = 0;

__global__ void __launch_bounds__(QTHREADS, 4)
vq_fused_kernel(const float* __restrict__ x,
                const float* __restrict__ emb,
                float* __restrict__ out,
                int n, int write_loss) {
    __shared__ float sval[NEMB];
    __shared__ int   sidx[NEMB];
    __shared__ short lut[LUT_SIZE];
    __shared__ int   s_rank[32];
    __shared__ float s_loss;

    const int tid = threadIdx.x;

    // ---- Prefetch this thread's single element (independent of codebook) --
    const int  idx  = blockIdx.x * QTHREADS + tid;
    const bool live = (idx < n);
    float xv = 0.0f;
    if (live) xv = x[idx];

    // ---- Phase 1: parallel rank sort of the codebook (blocks 0..15) -------
    // Sorter blocks are bids 0..15 -> guaranteed resident in wave 1 and
    // dependent on nothing, so the flag always gets set; spinners (resident
    // or later-wave) always make progress. Deadlock-free for any grid size.
    if (blockIdx.x < SORT_BLOCKS) {
        if (tid < 32) s_rank[tid] = 0;
        __syncthreads();

        // 32 codewords per block; 16 threads per codeword, each scanning a
        // 32-value (8 x float4) segment of the 512-entry codebook.
        const int cw_local = tid >> 4;                    // 0..31
        const int cw       = blockIdx.x * 32 + cw_local;  // original index
        const int seg      = tid & 15;                    // 0..15
        const float cv = __ldg(&emb[cw]);

        const float4* e4 = reinterpret_cast<const float4*>(emb);
        int partial = 0;
        #pragma unroll
        for (int q4 = 0; q4 < 8; q4++) {
            const int j4 = seg * 8 + q4;
            const float4 e = __ldg(&e4[j4]);
            const int j = j4 * 4;
            partial += (int)(e.x < cv) + (int)((e.x == cv) && (j + 0 < cw));
            partial += (int)(e.y < cv) + (int)((e.y == cv) && (j + 1 < cw));
            partial += (int)(e.z < cv) + (int)((e.z == cv) && (j + 2 < cw));
            partial += (int)(e.w < cv) + (int)((e.w == cv) && (j + 3 < cw));
        }
        atomicAdd(&s_rank[cw_local], partial);
        __syncthreads();

        if (tid < 32) {
            const int mycw = blockIdx.x * 32 + tid;
            const int r = s_rank[tid];         // exact permutation (keys unique)
            g_sorted_val[r] = __ldg(&emb[mycw]);
            g_sorted_idx[r] = mycw;
            __threadfence();                   // writers only: publish before flag
        }
        __syncthreads();
        if (tid == 0) atomicAdd(&g_ready, 1u);
    }

    // ---- Phase 2: wait for sorted codebook (plain-load spin, no RMW) ------
    if (tid == 0) {
        volatile unsigned int* rp = &g_ready;
        while (*rp < SORT_BLOCKS) { }
        s_loss = 0.0f;
    }
    __syncthreads();

    {
        // one element per thread: tid covers [0, NEMB) twice over 512 threads
        sval[tid & (NEMB - 1)] = __ldcg(&g_sorted_val[tid & (NEMB - 1)]);
        sidx[tid & (NEMB - 1)] = __ldcg(&g_sorted_idx[tid & (NEMB - 1)]);
    }
    __syncthreads();

    // ---- Build bucket LUT: lut[k] = lower_bound(sval, edge_k) -------------
    // Each thread owns LUT_CHUNK consecutive buckets: ONE binary search for
    // its first edge, then monotone incremental advance for the rest.
    const float vmin = sval[0];
    const float vmax = sval[NEMB - 1];
    const float rng  = vmax - vmin;
    const float inv  = (rng > 0.0f) ? (float)LUT_SIZE / rng : 0.0f;
    const float step = (rng > 0.0f) ? rng / (float)LUT_SIZE : 0.0f;

    {
        const int k0 = tid * LUT_CHUNK;
        const float edge0 = vmin + (float)k0 * step;
        int lo = 0, hi = NEMB;
        #pragma unroll
        for (int it = 0; it < 10; it++) {
            const int mid = (lo + hi) >> 1;
            if (hi > lo) { if (sval[mid] < edge0) lo = mid + 1; else hi = mid; }
        }
        #pragma unroll
        for (int j = 0; j < LUT_CHUNK; j++) {
            const float edge = vmin + (float)(k0 + j) * step;
            while (lo < NEMB && sval[lo] < edge) lo++;
            lut[k0 + j] = (short)lo;
        }
    }
    __syncthreads();

    // ---- Quantize this thread's element ------------------------------------
    float local = 0.0f;

    if (live) {
        int k = (int)((xv - vmin) * inv);
        k = min(max(k - 1, 0), LUT_SIZE - 1);   // -1: margin vs fp rounding
        int lo = (int)lut[k];
        while (lo < NEMB && sval[lo] < xv) lo++;

        float q, d2;
        if (lo == 0) {
            q = sval[0];
            const float d = __fadd_rn(xv, -q);
            d2 = __fmul_rn(d, d);
        } else if (lo == NEMB) {
            q = sval[NEMB - 1];
            const float d = __fadd_rn(xv, -q);
            d2 = __fmul_rn(d, d);
        } else {
            const float a  = sval[lo - 1];
            const float b  = sval[lo];
            const float da = __fadd_rn(xv, -a);
            const float db = __fadd_rn(xv, -b);
            const float da2 = __fmul_rn(da, da);
            const float db2 = __fmul_rn(db, db);
            bool pick_a;
            if (da2 < db2)      pick_a = true;
            else if (db2 < da2) pick_a = false;
            else                pick_a = (sidx[lo - 1] < sidx[lo]);
            q  = pick_a ? a   : b;
            d2 = pick_a ? da2 : db2;
        }
        out[idx] = q;
        local = d2;
    }

    // ---- Loss reduction -----------------------------------------------------
    #pragma unroll
    for (int off = 16; off > 0; off >>= 1)
        local += __shfl_xor_sync(0xFFFFFFFFu, local, off);
    if ((tid & 31) == 0)
        atomicAdd(&s_loss, local);
    __syncthreads();

    // ---- Phase 3: last block finalizes + resets state (graph replay) -------
    if (tid == 0) {
        atomicAdd(&g_loss_accum, s_loss);
        __threadfence();
        const unsigned t = atomicAdd(&g_done, 1u);
        if (t == (unsigned)(gridDim.x - 1)) {
            const float total = atomicAdd(&g_loss_accum, 0.0f);
            if (write_loss)
                out[n] = 1.25f * total / (float)n;
            g_loss_accum = 0.0f;
            g_ready = 0;
            g_done  = 0;
        }
    }
}

extern "C" void kernel_launch(void* const* d_in, const int* in_sizes, int n_in,
                              void* d_out, int out_size) {
    const float* x   = (const float*)d_in[0];   // pre_quantized, 16*1*128*128
    const float* emb = (const float*)d_in[1];   // emb_weight, 512*1
    float* out = (float*)d_out;

    const int n = in_sizes[0];                  // 262144
    const int write_loss = (out_size > n) ? 1 : 0;

    vq_fused_kernel<<<QBLOCKS, QTHREADS>>>(x, emb, out, n, write_loss);
}

// round 11
// speedup vs baseline: 1.4724x; 1.4724x over previous
#include <cuda_runtime.h>

#define NEMB      512
#define QBLOCKS   128          // every block sorts 4 codewords; all-to-all flag
#define QTHREADS  512
#define CW_PER_BLOCK (NEMB / QBLOCKS)        // 4
#define LUT_SIZE  8192
#define LUT_CHUNK (LUT_SIZE / QTHREADS)      // 16 buckets per thread

__device__ float        g_sorted_val[NEMB];
__device__ int          g_sorted_idx[NEMB];
__device__ float        g_loss_accum = 0.0f;
__device__ unsigned int g_ready = 0;
__device__ unsigned int g_done  = 0;

__global__ void __launch_bounds__(QTHREADS, 2)
vq_fused_kernel(const float* __restrict__ x,
                const float* __restrict__ emb,
                float* __restrict__ out,
                int n, int write_loss) {
    __shared__ float s_emb[NEMB];
    __shared__ float sval[NEMB];
    __shared__ int   sidx[NEMB];
    __shared__ short lut[LUT_SIZE];
    __shared__ int   s_rank[CW_PER_BLOCK];
    __shared__ float s_loss;

    const int tid = threadIdx.x;

    // ---- Prefetch this thread's 4 elements (independent of codebook) ------
    const int c    = blockIdx.x * QTHREADS + tid;   // chunk id
    const int base = c * 4;
    const bool full = (base + 3 < n);
    float4 v = make_float4(0.f, 0.f, 0.f, 0.f);
    if (full) v = *reinterpret_cast<const float4*>(x + base);

    // ---- Phase 1: EVERY block rank-sorts its 4 codewords -------------------
    // Stage codebook in shared (128 LDG.128/block, not 4096), scan via LDS.
    if (tid < CW_PER_BLOCK) s_rank[tid] = 0;
    if (tid < NEMB / 4) {
        const float4 e = __ldg(&reinterpret_cast<const float4*>(emb)[tid]);
        reinterpret_cast<float4*>(s_emb)[tid] = e;
    }
    __syncthreads();

    {
        const int g  = tid >> 7;                         // 0..3 codeword group
        const int cw = blockIdx.x * CW_PER_BLOCK + g;    // original index
        const int l  = tid & 127;                        // lane in group
        const float cv = s_emb[cw];
        const float4 e = reinterpret_cast<const float4*>(s_emb)[l]; // conflict-free
        const int j = l * 4;
        int partial = 0;
        partial += (int)(e.x < cv) + (int)((e.x == cv) && (j + 0 < cw));
        partial += (int)(e.y < cv) + (int)((e.y == cv) && (j + 1 < cw));
        partial += (int)(e.z < cv) + (int)((e.z == cv) && (j + 2 < cw));
        partial += (int)(e.w < cv) + (int)((e.w == cv) && (j + 3 < cw));
        atomicAdd(&s_rank[g], partial);
    }
    __syncthreads();

    if (tid < CW_PER_BLOCK) {
        const int mycw = blockIdx.x * CW_PER_BLOCK + tid;
        const int r = s_rank[tid];             // exact permutation (keys unique)
        g_sorted_val[r] = s_emb[mycw];
        g_sorted_idx[r] = mycw;
        __threadfence();                       // publish before flag
    }
    __syncthreads();
    if (tid == 0) atomicAdd(&g_ready, 1u);

    // ---- Phase 2: wait until ALL blocks published their slice -------------
    if (tid == 0) {
        volatile unsigned int* rp = &g_ready;
        while (*rp < QBLOCKS) { }
        s_loss = 0.0f;
    }
    __syncthreads();

    // Vectorized copy of sorted codebook from L2 (the coherence point).
    if (tid < NEMB / 4) {
        const float4 vv = __ldcg(&reinterpret_cast<const float4*>(g_sorted_val)[tid]);
        reinterpret_cast<float4*>(sval)[tid] = vv;
    } else if (tid < NEMB / 2) {
        const int t = tid - NEMB / 4;
        const int4 ii = __ldcg(&reinterpret_cast<const int4*>(g_sorted_idx)[t]);
        reinterpret_cast<int4*>(sidx)[t] = ii;
    }
    __syncthreads();

    // ---- Build bucket LUT: lut[k] = lower_bound(sval, edge_k) -------------
    const float vmin = sval[0];
    const float vmax = sval[NEMB - 1];
    const float rng  = vmax - vmin;
    const float inv  = (rng > 0.0f) ? (float)LUT_SIZE / rng : 0.0f;
    const float step = (rng > 0.0f) ? rng / (float)LUT_SIZE : 0.0f;

    {
        const int k0 = tid * LUT_CHUNK;
        const float edge0 = vmin + (float)k0 * step;
        int lo = 0, hi = NEMB;
        #pragma unroll
        for (int it = 0; it < 10; it++) {
            const int mid = (lo + hi) >> 1;
            if (hi > lo) { if (sval[mid] < edge0) lo = mid + 1; else hi = mid; }
        }
        #pragma unroll
        for (int j = 0; j < LUT_CHUNK; j++) {
            const float edge = vmin + (float)(k0 + j) * step;
            while (lo < NEMB && sval[lo] < edge) lo++;
            lut[k0 + j] = (short)lo;
        }
    }
    __syncthreads();

    // ---- Quantize: bucket start + short upward scan to true lower_bound ---
    float local = 0.0f;

    if (full) {
        float vv[4] = {v.x, v.y, v.z, v.w};
        float qq[4];
        #pragma unroll
        for (int e = 0; e < 4; e++) {
            const float xv = vv[e];
            int k = (int)((xv - vmin) * inv);
            k = min(max(k - 1, 0), LUT_SIZE - 1);   // -1: margin vs fp rounding
            int lo = (int)lut[k];
            while (lo < NEMB && sval[lo] < xv) lo++;

            float q, d2;
            if (lo == 0) {
                q = sval[0];
                const float d = __fadd_rn(xv, -q);
                d2 = __fmul_rn(d, d);
            } else if (lo == NEMB) {
                q = sval[NEMB - 1];
                const float d = __fadd_rn(xv, -q);
                d2 = __fmul_rn(d, d);
            } else {
                const float a  = sval[lo - 1];
                const float b  = sval[lo];
                const float da = __fadd_rn(xv, -a);
                const float db = __fadd_rn(xv, -b);
                const float da2 = __fmul_rn(da, da);
                const float db2 = __fmul_rn(db, db);
                bool pick_a;
                if (da2 < db2)      pick_a = true;
                else if (db2 < da2) pick_a = false;
                else                pick_a = (sidx[lo - 1] < sidx[lo]);
                q  = pick_a ? a   : b;
                d2 = pick_a ? da2 : db2;
            }
            qq[e] = q;
            local += d2;
        }
        float4 o;
        o.x = qq[0]; o.y = qq[1]; o.z = qq[2]; o.w = qq[3];
        *reinterpret_cast<float4*>(out + base) = o;
    } else {
        for (int i = base; i < n && i < base + 4; i++) {
            const float xv = x[i];
            int k = (int)((xv - vmin) * inv);
            k = min(max(k - 1, 0), LUT_SIZE - 1);
            int lo = (int)lut[k];
            while (lo < NEMB && sval[lo] < xv) lo++;
            float q, d2;
            if (lo == 0) {
                q = sval[0];
                const float d = __fadd_rn(xv, -q); d2 = __fmul_rn(d, d);
            } else if (lo == NEMB) {
                q = sval[NEMB - 1];
                const float d = __fadd_rn(xv, -q); d2 = __fmul_rn(d, d);
            } else {
                const float a  = sval[lo - 1];
                const float b  = sval[lo];
                const float da = __fadd_rn(xv, -a);
                const float db = __fadd_rn(xv, -b);
                const float da2 = __fmul_rn(da, da);
                const float db2 = __fmul_rn(db, db);
                bool pick_a;
                if (da2 < db2)      pick_a = true;
                else if (db2 < da2) pick_a = false;
                else                pick_a = (sidx[lo - 1] < sidx[lo]);
                q  = pick_a ? a   : b;
                d2 = pick_a ? da2 : db2;
            }
            out[i] = q;
            local += d2;
        }
    }

    // ---- Loss reduction -----------------------------------------------------
    #pragma unroll
    for (int off = 16; off > 0; off >>= 1)
        local += __shfl_xor_sync(0xFFFFFFFFu, local, off);
    if ((tid & 31) == 0)
        atomicAdd(&s_loss, local);
    __syncthreads();

    // ---- Phase 3: last block finalizes + resets state (graph replay) -------
    if (tid == 0) {
        atomicAdd(&g_loss_accum, s_loss);
        __threadfence();
        const unsigned t = atomicAdd(&g_done, 1u);
        if (t == (unsigned)(gridDim.x - 1)) {
            const float total = atomicAdd(&g_loss_accum, 0.0f);
            if (write_loss)
                out[n] = 1.25f * total / (float)n;
            g_loss_accum = 0.0f;
            g_ready = 0;
            g_done  = 0;
        }
    }
}

extern "C" void kernel_launch(void* const* d_in, const int* in_sizes, int n_in,
                              void* d_out, int out_size) {
    const float* x   = (const float*)d_in[0];   // pre_quantized, 16*1*128*128
    const float* emb = (const float*)d_in[1];   // emb_weight, 512*1
    float* out = (float*)d_out;

    const int n = in_sizes[0];                  // 262144
    const int write_loss = (out_size > n) ? 1 : 0;

    vq_fused_kernel<<<QBLOCKS, QTHREADS>>>(x, emb, out, n, write_loss);
}